// round 2
// baseline (speedup 1.0000x reference)
#include <cuda_runtime.h>

#define NN 50000
#define NE 800000
#define D  128
#define NG 512

// Scratch (no device allocation allowed -> __device__ globals)
__device__ __align__(16) float g_agg[NN * D];
__device__ __align__(16) float g_t  [NN * D];
__device__ __align__(16) float g_h  [NN * D];
__device__ __align__(16) float g_pool[NG * D];

// ---------------------------------------------------------------------------
// zero: grid-stride float4 stores
__global__ void zero_kernel(float* __restrict__ p, int n4) {
    float4 z = make_float4(0.f, 0.f, 0.f, 0.f);
    for (int i = blockIdx.x * blockDim.x + threadIdx.x; i < n4;
         i += gridDim.x * blockDim.x)
        reinterpret_cast<float4*>(p)[i] = z;
}

// ---------------------------------------------------------------------------
// scatter-add: one warp per edge; lane handles 4 floats (float4 gather +
// red.global.add.v4.f32 -> 16B vector reduction, no return trip).
// NOTE: edge indices are int32 (JAX default x64-disabled downcasts int64).
__global__ void scatter_kernel(const float* __restrict__ hin,
                               const int* __restrict__ src,
                               const int* __restrict__ dst,
                               float* __restrict__ agg) {
    int lane = threadIdx.x & 31;
    int warp = (blockIdx.x * blockDim.x + threadIdx.x) >> 5;
    int nwarp = (gridDim.x * blockDim.x) >> 5;
    for (int e = warp; e < NE; e += nwarp) {
        int s = 0, d = 0;
        if (lane == 0) { s = src[e]; d = dst[e]; }
        s = __shfl_sync(0xffffffffu, s, 0);
        d = __shfl_sync(0xffffffffu, d, 0);
        float4 v = *reinterpret_cast<const float4*>(hin + (size_t)s * D + lane * 4);
        float* p = agg + (size_t)d * D + lane * 4;
        asm volatile("red.global.add.v4.f32 [%0], {%1,%2,%3,%4};"
                     :: "l"(p), "f"(v.x), "f"(v.y), "f"(v.z), "f"(v.w)
                     : "memory");
    }
}

// ---------------------------------------------------------------------------
// pool: one warp per node, vector reduction into g_pool[batch[n]]
__global__ void pool_kernel(const float* __restrict__ hin,
                            const int* __restrict__ batch,
                            float* __restrict__ pool) {
    int lane = threadIdx.x & 31;
    int warp = (blockIdx.x * blockDim.x + threadIdx.x) >> 5;
    int nwarp = (gridDim.x * blockDim.x) >> 5;
    for (int n = warp; n < NN; n += nwarp) {
        int b = 0;
        if (lane == 0) b = batch[n];
        b = __shfl_sync(0xffffffffu, b, 0);
        float4 v = *reinterpret_cast<const float4*>(hin + (size_t)n * D + lane * 4);
        float* p = pool + (size_t)b * D + lane * 4;
        asm volatile("red.global.add.v4.f32 [%0], {%1,%2,%3,%4};"
                     :: "l"(p), "f"(v.x), "f"(v.y), "f"(v.z), "f"(v.w)
                     : "memory");
    }
}

// ---------------------------------------------------------------------------
// Fused GEMM: out = relu((A [+ A2]) @ W + bias), K = N = 128.
// Block: 256 threads, 64-row tile, all 128 output cols.
// SMEM: W fully resident (64 KB) + A tile 64x128 padded to 132 (33 KB).
#define ASTRIDE 132
template <bool ADD2>
__global__ __launch_bounds__(256, 1)
void gemm_kernel(const float* __restrict__ A, const float* __restrict__ A2,
                 const float* __restrict__ W, const float* __restrict__ bias,
                 float* __restrict__ out, int M) {
    extern __shared__ float sm[];
    float* Ws = sm;                 // [128][128]
    float* As = sm + 128 * 128;     // [64][ASTRIDE]

    int tid = threadIdx.x;
    int row0 = blockIdx.x * 64;

    // Load W (16384 floats, float4-coalesced)
#pragma unroll
    for (int j = 0; j < 16; j++) {
        int i4 = tid + 256 * j;
        reinterpret_cast<float4*>(Ws)[i4] =
            reinterpret_cast<const float4*>(W)[i4];
    }
    // Load A tile (optionally fused + A2), 8192 floats
#pragma unroll
    for (int j = 0; j < 8; j++) {
        int i4 = tid + 256 * j;          // float4 index in 64x128 tile
        int idx = i4 * 4;
        int r = idx >> 7;
        int k = idx & 127;
        int gr = row0 + r;
        float4 v = make_float4(0.f, 0.f, 0.f, 0.f);
        if (gr < M) {
            v = *reinterpret_cast<const float4*>(A + (size_t)gr * D + k);
            if (ADD2) {
                float4 w = *reinterpret_cast<const float4*>(A2 + (size_t)gr * D + k);
                v.x += w.x; v.y += w.y; v.z += w.z; v.w += w.w;
            }
        }
        *reinterpret_cast<float4*>(&As[r * ASTRIDE + k]) = v;
    }
    __syncthreads();

    int rg = tid >> 4;   // 0..15 -> rows rg*4 .. rg*4+3
    int cg = tid & 15;   // 0..15 -> cols cg*8 .. cg*8+7

    float acc[4][8];
#pragma unroll
    for (int i = 0; i < 4; i++)
#pragma unroll
        for (int j = 0; j < 8; j++) acc[i][j] = 0.f;

#pragma unroll 8
    for (int k = 0; k < 128; k++) {
        float4 b0 = *reinterpret_cast<const float4*>(&Ws[k * 128 + cg * 8]);
        float4 b1 = *reinterpret_cast<const float4*>(&Ws[k * 128 + cg * 8 + 4]);
#pragma unroll
        for (int i = 0; i < 4; i++) {
            float a = As[(rg * 4 + i) * ASTRIDE + k];
            acc[i][0] += a * b0.x; acc[i][1] += a * b0.y;
            acc[i][2] += a * b0.z; acc[i][3] += a * b0.w;
            acc[i][4] += a * b1.x; acc[i][5] += a * b1.y;
            acc[i][6] += a * b1.z; acc[i][7] += a * b1.w;
        }
    }

    float4 bv0 = *reinterpret_cast<const float4*>(bias + cg * 8);
    float4 bv1 = *reinterpret_cast<const float4*>(bias + cg * 8 + 4);
#pragma unroll
    for (int i = 0; i < 4; i++) {
        int gr = row0 + rg * 4 + i;
        if (gr < M) {
            float4 o0, o1;
            o0.x = fmaxf(acc[i][0] + bv0.x, 0.f);
            o0.y = fmaxf(acc[i][1] + bv0.y, 0.f);
            o0.z = fmaxf(acc[i][2] + bv0.z, 0.f);
            o0.w = fmaxf(acc[i][3] + bv0.w, 0.f);
            o1.x = fmaxf(acc[i][4] + bv1.x, 0.f);
            o1.y = fmaxf(acc[i][5] + bv1.y, 0.f);
            o1.z = fmaxf(acc[i][6] + bv1.z, 0.f);
            o1.w = fmaxf(acc[i][7] + bv1.w, 0.f);
            *reinterpret_cast<float4*>(out + (size_t)gr * D + cg * 8)     = o0;
            *reinterpret_cast<float4*>(out + (size_t)gr * D + cg * 8 + 4) = o1;
        }
    }
}

// ---------------------------------------------------------------------------
extern "C" void kernel_launch(void* const* d_in, const int* in_sizes, int n_in,
                              void* d_out, int out_size) {
    const float* x = (const float*)d_in[0];
    const int* ei = (const int*)d_in[1];       // int32 (JAX x64 disabled)
    const int* batch = (const int*)d_in[2];    // int32
    const float* W1a = (const float*)d_in[3];
    const float* b1a = (const float*)d_in[4];
    const float* W1b = (const float*)d_in[5];
    const float* b1b = (const float*)d_in[6];
    const float* W2a = (const float*)d_in[7];
    const float* b2a = (const float*)d_in[8];
    const float* W2b = (const float*)d_in[9];
    const float* b2b = (const float*)d_in[10];
    const float* Wfc = (const float*)d_in[11];
    const float* bfc = (const float*)d_in[12];
    float* out = (float*)d_out;

    const int* src = ei;
    const int* dst = ei + NE;

    float *agg, *t, *h, *pool;
    cudaGetSymbolAddress((void**)&agg, g_agg);
    cudaGetSymbolAddress((void**)&t, g_t);
    cudaGetSymbolAddress((void**)&h, g_h);
    cudaGetSymbolAddress((void**)&pool, g_pool);

    const int SMEM = (128 * 128 + 64 * ASTRIDE) * (int)sizeof(float); // 99328 B
    cudaFuncSetAttribute(gemm_kernel<true>,
                         cudaFuncAttributeMaxDynamicSharedMemorySize, SMEM);
    cudaFuncSetAttribute(gemm_kernel<false>,
                         cudaFuncAttributeMaxDynamicSharedMemorySize, SMEM);

    int gemm_grid = (NN + 63) / 64;          // 782
    int fc_grid = (NG + 63) / 64;            // 8

    // Layer 1
    zero_kernel<<<1024, 256>>>(agg, NN * D / 4);
    scatter_kernel<<<4096, 256>>>(x, src, dst, agg);
    gemm_kernel<true ><<<gemm_grid, 256, SMEM>>>(x, agg, W1a, b1a, t, NN);
    gemm_kernel<false><<<gemm_grid, 256, SMEM>>>(t, nullptr, W1b, b1b, h, NN);

    // Layer 2
    zero_kernel<<<1024, 256>>>(agg, NN * D / 4);
    scatter_kernel<<<4096, 256>>>(h, src, dst, agg);
    gemm_kernel<true ><<<gemm_grid, 256, SMEM>>>(h, agg, W2a, b2a, t, NN);
    gemm_kernel<false><<<gemm_grid, 256, SMEM>>>(t, nullptr, W2b, b2b, h, NN);

    // Global add pool + FC head
    zero_kernel<<<64, 256>>>(pool, NG * D / 4);
    pool_kernel<<<2048, 256>>>(h, batch, pool);
    gemm_kernel<false><<<fc_grid, 256, SMEM>>>(pool, nullptr, Wfc, bfc, out, NG);
}

// round 3
// speedup vs baseline: 1.2647x; 1.2647x over previous
#include <cuda_runtime.h>

#define NN 50000
#define NE 800000
#define D  128
#define NG 512
#define AS 132   // As row stride (floats), 16B-aligned, pad vs 128

// Scratch (no device allocation allowed -> __device__ globals)
__device__ __align__(16) float g_agg[NN * D];
__device__ __align__(16) float g_t  [NN * D];
__device__ __align__(16) float g_h  [NN * D];
__device__ __align__(16) float g_pool[NG * D];

// ---------------------------------------------------------------------------
__global__ void zero_kernel(float* __restrict__ p, int n4) {
    float4 z = make_float4(0.f, 0.f, 0.f, 0.f);
    for (int i = blockIdx.x * blockDim.x + threadIdx.x; i < n4;
         i += gridDim.x * blockDim.x)
        reinterpret_cast<float4*>(p)[i] = z;
}

// ---------------------------------------------------------------------------
// scatter-add: one warp per edge; float4 gather + red.global.add.v4.f32
__global__ void scatter_kernel(const float* __restrict__ hin,
                               const int* __restrict__ src,
                               const int* __restrict__ dst,
                               float* __restrict__ agg) {
    int lane = threadIdx.x & 31;
    int warp = (blockIdx.x * blockDim.x + threadIdx.x) >> 5;
    int nwarp = (gridDim.x * blockDim.x) >> 5;
    for (int e = warp; e < NE; e += nwarp) {
        int s = 0, d = 0;
        if (lane == 0) { s = src[e]; d = dst[e]; }
        s = __shfl_sync(0xffffffffu, s, 0);
        d = __shfl_sync(0xffffffffu, d, 0);
        float4 v = *reinterpret_cast<const float4*>(hin + (size_t)s * D + lane * 4);
        float* p = agg + (size_t)d * D + lane * 4;
        asm volatile("red.global.add.v4.f32 [%0], {%1,%2,%3,%4};"
                     :: "l"(p), "f"(v.x), "f"(v.y), "f"(v.z), "f"(v.w)
                     : "memory");
    }
}

// ---------------------------------------------------------------------------
__global__ void pool_kernel(const float* __restrict__ hin,
                            const int* __restrict__ batch,
                            float* __restrict__ pool) {
    int lane = threadIdx.x & 31;
    int warp = (blockIdx.x * blockDim.x + threadIdx.x) >> 5;
    int nwarp = (gridDim.x * blockDim.x) >> 5;
    for (int n = warp; n < NN; n += nwarp) {
        int b = 0;
        if (lane == 0) b = batch[n];
        b = __shfl_sync(0xffffffffu, b, 0);
        float4 v = *reinterpret_cast<const float4*>(hin + (size_t)n * D + lane * 4);
        float* p = pool + (size_t)b * D + lane * 4;
        asm volatile("red.global.add.v4.f32 [%0], {%1,%2,%3,%4};"
                     :: "l"(p), "f"(v.x), "f"(v.y), "f"(v.z), "f"(v.w)
                     : "memory");
    }
}

// ---------------------------------------------------------------------------
// Packed f32x2 helpers (sm_103a FFMA2 path, only reachable via PTX)
__device__ __forceinline__ unsigned long long pk2(float x, float y) {
    unsigned long long r;
    asm("mov.b64 %0, {%1, %2};" : "=l"(r) : "f"(x), "f"(y));
    return r;
}
__device__ __forceinline__ void upk2(unsigned long long v, float& x, float& y) {
    asm("mov.b64 {%0, %1}, %2;" : "=f"(x), "=f"(y) : "l"(v));
}
#define FMA2(d, a, b) \
    asm("fma.rn.f32x2 %0, %1, %2, %0;" : "+l"(d) : "l"(a), "l"(b))

// ---------------------------------------------------------------------------
// Persistent fused GEMM: out = relu((A [+ A2]) @ W + bias), K = N = 128.
// Block 256 threads, 128x128 tile, 8x8 register tile per thread, fma.rn.f32x2.
// W resident in smem for the whole kernel; A tile reloaded per tile.
template <bool ADD2>
__global__ __launch_bounds__(256, 1)
void gemm_kernel(const float* __restrict__ A, const float* __restrict__ A2,
                 const float* __restrict__ W, const float* __restrict__ bias,
                 float* __restrict__ out, int M) {
    extern __shared__ float sm[];
    float* Ws = sm;                  // [128][128] = 64KB
    float* As = sm + 128 * 128;      // [128][AS]

    int tid = threadIdx.x;
    int tr = tid >> 4;               // 0..15 -> rows tr*8..tr*8+7
    int tc = tid & 15;               // 0..15 -> cols tc*8..tc*8+7

    // Load W once (16384 floats, float4-coalesced)
#pragma unroll
    for (int j = 0; j < 16; j++) {
        int i4 = tid + 256 * j;
        reinterpret_cast<float4*>(Ws)[i4] =
            reinterpret_cast<const float4*>(W)[i4];
    }

    // Bias pairs (tile-invariant, hoisted)
    float4 bb0 = *reinterpret_cast<const float4*>(bias + tc * 8);
    float4 bb1 = *reinterpret_cast<const float4*>(bias + tc * 8 + 4);
    float bs[8] = {bb0.x, bb0.y, bb0.z, bb0.w, bb1.x, bb1.y, bb1.z, bb1.w};

    int ntiles = (M + 127) >> 7;
    for (int tile = blockIdx.x; tile < ntiles; tile += gridDim.x) {
        int row0 = tile << 7;
        __syncthreads();             // As reuse across tile iterations

        // Load A tile (optionally fused + A2): 4096 float4
#pragma unroll
        for (int j = 0; j < 16; j++) {
            int i4 = tid + 256 * j;
            int r = i4 >> 5;         // 32 float4 per row
            int kq = i4 & 31;
            int gr = row0 + r;
            float4 v = make_float4(0.f, 0.f, 0.f, 0.f);
            if (gr < M) {
                v = reinterpret_cast<const float4*>(A + (size_t)gr * D)[kq];
                if (ADD2) {
                    float4 w = reinterpret_cast<const float4*>(A2 + (size_t)gr * D)[kq];
                    v.x += w.x; v.y += w.y; v.z += w.z; v.w += w.w;
                }
            }
            *reinterpret_cast<float4*>(&As[r * AS + kq * 4]) = v;
        }
        __syncthreads();

        unsigned long long acc[8][4];
#pragma unroll
        for (int i = 0; i < 8; i++)
#pragma unroll
            for (int j = 0; j < 4; j++) acc[i][j] = 0ull;

        const float* arow = As + tr * 8 * AS;
#pragma unroll 8
        for (int k = 0; k < 128; k++) {
            float4 b0 = *reinterpret_cast<const float4*>(&Ws[k * 128 + tc * 8]);
            float4 b1 = *reinterpret_cast<const float4*>(&Ws[k * 128 + tc * 8 + 4]);
            unsigned long long bp0 = pk2(b0.x, b0.y);
            unsigned long long bp1 = pk2(b0.z, b0.w);
            unsigned long long bp2 = pk2(b1.x, b1.y);
            unsigned long long bp3 = pk2(b1.z, b1.w);
#pragma unroll
            for (int i = 0; i < 8; i++) {
                float a = arow[i * AS + k];
                unsigned long long aa = pk2(a, a);
                FMA2(acc[i][0], aa, bp0);
                FMA2(acc[i][1], aa, bp1);
                FMA2(acc[i][2], aa, bp2);
                FMA2(acc[i][3], aa, bp3);
            }
        }

        // Epilogue: unpack, bias, relu, store
#pragma unroll
        for (int i = 0; i < 8; i++) {
            int gr = row0 + tr * 8 + i;
            if (gr < M) {
                float o[8];
#pragma unroll
                for (int j = 0; j < 4; j++)
                    upk2(acc[i][j], o[2 * j], o[2 * j + 1]);
                float4 s0, s1;
                s0.x = fmaxf(o[0] + bs[0], 0.f);
                s0.y = fmaxf(o[1] + bs[1], 0.f);
                s0.z = fmaxf(o[2] + bs[2], 0.f);
                s0.w = fmaxf(o[3] + bs[3], 0.f);
                s1.x = fmaxf(o[4] + bs[4], 0.f);
                s1.y = fmaxf(o[5] + bs[5], 0.f);
                s1.z = fmaxf(o[6] + bs[6], 0.f);
                s1.w = fmaxf(o[7] + bs[7], 0.f);
                *reinterpret_cast<float4*>(out + (size_t)gr * D + tc * 8)     = s0;
                *reinterpret_cast<float4*>(out + (size_t)gr * D + tc * 8 + 4) = s1;
            }
        }
    }
}

// ---------------------------------------------------------------------------
extern "C" void kernel_launch(void* const* d_in, const int* in_sizes, int n_in,
                              void* d_out, int out_size) {
    const float* x = (const float*)d_in[0];
    const int* ei = (const int*)d_in[1];       // int32 (JAX x64 disabled)
    const int* batch = (const int*)d_in[2];    // int32
    const float* W1a = (const float*)d_in[3];
    const float* b1a = (const float*)d_in[4];
    const float* W1b = (const float*)d_in[5];
    const float* b1b = (const float*)d_in[6];
    const float* W2a = (const float*)d_in[7];
    const float* b2a = (const float*)d_in[8];
    const float* W2b = (const float*)d_in[9];
    const float* b2b = (const float*)d_in[10];
    const float* Wfc = (const float*)d_in[11];
    const float* bfc = (const float*)d_in[12];
    float* out = (float*)d_out;

    const int* src = ei;
    const int* dst = ei + NE;

    float *agg, *t, *h, *pool;
    cudaGetSymbolAddress((void**)&agg, g_agg);
    cudaGetSymbolAddress((void**)&t, g_t);
    cudaGetSymbolAddress((void**)&h, g_h);
    cudaGetSymbolAddress((void**)&pool, g_pool);

    const int SMEM = (128 * 128 + 128 * AS) * (int)sizeof(float); // 133120 B
    cudaFuncSetAttribute(gemm_kernel<true>,
                         cudaFuncAttributeMaxDynamicSharedMemorySize, SMEM);
    cudaFuncSetAttribute(gemm_kernel<false>,
                         cudaFuncAttributeMaxDynamicSharedMemorySize, SMEM);

    int gemm_grid = 148;                       // persistent, tiles looped
    int fc_grid = (NG + 127) / 128;            // 4

    // Layer 1
    zero_kernel<<<1024, 256>>>(agg, NN * D / 4);
    scatter_kernel<<<4096, 256>>>(x, src, dst, agg);
    gemm_kernel<true ><<<gemm_grid, 256, SMEM>>>(x, agg, W1a, b1a, t, NN);
    gemm_kernel<false><<<gemm_grid, 256, SMEM>>>(t, nullptr, W1b, b1b, h, NN);

    // Layer 2
    zero_kernel<<<1024, 256>>>(agg, NN * D / 4);
    scatter_kernel<<<4096, 256>>>(h, src, dst, agg);
    gemm_kernel<true ><<<gemm_grid, 256, SMEM>>>(h, agg, W2a, b2a, t, NN);
    gemm_kernel<false><<<gemm_grid, 256, SMEM>>>(t, nullptr, W2b, b2b, h, NN);

    // Global add pool + FC head
    zero_kernel<<<64, 256>>>(pool, NG * D / 4);
    pool_kernel<<<2048, 256>>>(h, batch, pool);
    gemm_kernel<false><<<fc_grid, 256, SMEM>>>(pool, nullptr, Wfc, bfc, out, NG);
}